// round 1
// baseline (speedup 1.0000x reference)
#include <cuda_runtime.h>
#include <math.h>
#include <stdint.h>

#define NATC 1024
#define DEGC 32
#define DC   128
#define RC   64
#define LC   3
#define BC   16
#define EC   (NATC*DEGC)      /* 32768 */
#define HDC  (DC/2)           /* 64 */
#define BNAT (BC*NATC)        /* 16384 */
#define BE   ((size_t)BC*EC)  /* 524288 */
#define M4   (4*BNAT)         /* 65536 */
#define MAXSP 512
#define LOG2C 0.69314718055994530942f

// ---------------- scratch (allocation-free: __device__ globals) ----------------
__device__ float g_feat4[(size_t)4*BNAT*DC];
__device__ float g_xw4 [(size_t)4*BNAT*DC];
__device__ float g_y4  [(size_t)4*BNAT*DC];
__device__ float g_t34 [(size_t)4*BNAT*DC];
__device__ float g_h4  [(size_t)4*BNAT*HDC];
__device__ float g_rbf [(size_t)BE*RC];
__device__ float g_s1  [(size_t)BE*DC];
__device__ float g_fb  [(size_t)BE*DC];
__device__ float g_d   [BE];
__device__ float g_ddot[(size_t)BE*3];
__device__ float g_Fsp [(size_t)BC*MAXSP*DC];
__device__ int   g_sidx[EC];
__device__ int   g_spList[MAXSP];
__device__ int   g_spCount;

// ---------------- math helpers ----------------
__device__ __forceinline__ float sspf(float x) {
    // softplus(x) - log(2), numerically stable
    return fmaxf(x, 0.f) + log1pf(expf(-fabsf(x))) - LOG2C;
}
__device__ __forceinline__ float sigf(float x) {
    return 1.f / (1.f + expf(-x));
}

// ---------------- prep ----------------
__global__ void prepResetK() { g_spCount = 0; }

__global__ void prepBuildK(const int* __restrict__ idx_i, const int* __restrict__ idx_j) {
    int e = blockIdx.x * blockDim.x + threadIdx.x;
    if (e >= EC) return;
    g_sidx[e] = -1;
    if (idx_i[e] == 0 || idx_j[e] == 0) {
        int p = atomicAdd(&g_spCount, 1);
        if (p < MAXSP) { g_spList[p] = e; g_sidx[e] = p; }
    }
}

__global__ void initK(const float* __restrict__ emb, const int* __restrict__ types) {
    int gid = blockIdx.x * blockDim.x + threadIdx.x;      // over BNAT*DC
    if (gid >= BNAT * DC) return;
    int nd = gid;                     // (b*NAT+n)*D + d
    int bn = nd / DC;
    int d  = nd - bn * DC;
    int ty = types[bn];
    const size_t TB = (size_t)BNAT * DC;
    g_feat4[gid]        = emb[(size_t)ty * DC + d];
    g_feat4[TB + gid]   = 0.f;
    g_feat4[2*TB + gid] = 0.f;
    g_feat4[3*TB + gid] = 0.f;
}

__global__ void distK(const float* __restrict__ pos,
                      const int* __restrict__ idx_i, const int* __restrict__ idx_j) {
    int gid = blockIdx.x * blockDim.x + threadIdx.x;      // over B*E
    if (gid >= (int)BE) return;
    int b = gid / EC, e = gid - b * EC;
    int i = idx_i[e], j = idx_j[e];
    const float* pi = pos + ((size_t)b * NATC + i) * 3;
    const float* pj = pos + ((size_t)b * NATC + j) * 3;
    float dx = pi[0]-pj[0], dy = pi[1]-pj[1], dz = pi[2]-pj[2];
    float dv = sqrtf(dx*dx + dy*dy + dz*dz + 1e-8f);
    g_d[gid] = dv;
    float c = (float)((i == 0) - (j == 0));
    float inv = c / dv;
    g_ddot[(size_t)gid*3 + 0] = dx * inv;
    g_ddot[(size_t)gid*3 + 1] = dy * inv;
    g_ddot[(size_t)gid*3 + 2] = dz * inv;
}

__global__ void rbfK(const float* __restrict__ centers, const float* __restrict__ gammaA, int l) {
    int gid = blockIdx.x * blockDim.x + threadIdx.x;      // over B*E*R
    if (gid >= (int)(BE * RC)) return;
    int be = gid >> 6;            // /RC
    int r  = gid & (RC - 1);
    float dv = g_d[be];
    float diff = dv - centers[l*RC + r];
    g_rbf[gid] = expf(-gammaA[l*RC + r] * diff * diff);
}

// ---------------- SGEMM: C[M,N] = A[M,K] @ B[K,N] (+bias on rows<biasRows)(+ssp)(+res) ----------
__global__ void __launch_bounds__(256) sgemmK(
    const float* __restrict__ A, const float* __restrict__ Bm, float* __restrict__ C,
    int M, int N, int K, const float* __restrict__ bias, int biasRows,
    const float* __restrict__ res, int act)
{
    __shared__ float As[16][128];
    __shared__ float Bs[16][128];
    const int tid = threadIdx.x;
    const int m0 = blockIdx.x * 128;
    const int n0 = blockIdx.y * 128;
    const int tx = tid & 15, ty = tid >> 4;
    const int aRow = tid >> 2, aCol = (tid & 3) << 2;
    const int bRow = tid >> 5, bCol = (tid & 31) << 2;
    float acc[8][8];
    #pragma unroll
    for (int i = 0; i < 8; i++)
        #pragma unroll
        for (int j = 0; j < 8; j++) acc[i][j] = 0.f;

    for (int k0 = 0; k0 < K; k0 += 16) {
        #pragma unroll
        for (int h = 0; h < 2; h++) {
            int r = aRow + h * 64;
            float4 v = *reinterpret_cast<const float4*>(A + (size_t)(m0 + r) * K + (k0 + aCol));
            As[aCol+0][r] = v.x; As[aCol+1][r] = v.y; As[aCol+2][r] = v.z; As[aCol+3][r] = v.w;
        }
        #pragma unroll
        for (int h = 0; h < 2; h++) {
            int r = bRow + h * 8;
            float4 v = make_float4(0.f, 0.f, 0.f, 0.f);
            if (n0 + bCol < N)
                v = *reinterpret_cast<const float4*>(Bm + (size_t)(k0 + r) * N + (n0 + bCol));
            *reinterpret_cast<float4*>(&Bs[r][bCol]) = v;
        }
        __syncthreads();
        #pragma unroll
        for (int k = 0; k < 16; k++) {
            float4 a0 = *reinterpret_cast<const float4*>(&As[k][ty*8]);
            float4 a1 = *reinterpret_cast<const float4*>(&As[k][ty*8 + 4]);
            float4 b0 = *reinterpret_cast<const float4*>(&Bs[k][tx*8]);
            float4 b1 = *reinterpret_cast<const float4*>(&Bs[k][tx*8 + 4]);
            float av[8] = {a0.x,a0.y,a0.z,a0.w,a1.x,a1.y,a1.z,a1.w};
            float bv[8] = {b0.x,b0.y,b0.z,b0.w,b1.x,b1.y,b1.z,b1.w};
            #pragma unroll
            for (int i = 0; i < 8; i++)
                #pragma unroll
                for (int j = 0; j < 8; j++)
                    acc[i][j] += av[i] * bv[j];
        }
        __syncthreads();
    }
    #pragma unroll
    for (int i = 0; i < 8; i++) {
        int row = m0 + ty*8 + i;
        bool useB = (bias != nullptr) && (row < biasRows);
        #pragma unroll
        for (int j = 0; j < 8; j++) {
            int col = n0 + tx*8 + j;
            if (col < N) {
                float v = acc[i][j];
                if (useB) v += bias[col];
                if (act == 1) v = sspf(v);
                if (res) v += res[(size_t)row * N + col];
                C[(size_t)row * N + col] = v;
            }
        }
    }
}

// ---------------- F(e) for special edges (tangent of edge MLP wrt d) ----------------
__global__ void fspK(const float* __restrict__ Wf1, const float* __restrict__ Wf2,
                     const float* __restrict__ centers, const float* __restrict__ gammaA, int l) {
    int s = blockIdx.x, b = blockIdx.y;
    int cnt = g_spCount; if (cnt > MAXSP) cnt = MAXSP;
    if (s >= cnt) return;
    int e = g_spList[s];
    int t = threadIdx.x;   // 0..127
    __shared__ float cva[RC];
    __shared__ float wk[DC];
    size_t be = (size_t)b * EC + e;
    float dv = g_d[be];
    if (t < RC) {
        float gm = gammaA[l*RC + t], cc = centers[l*RC + t];
        cva[t] = g_rbf[be*RC + t] * (-2.f * gm * (dv - cc));
    }
    __syncthreads();
    float v = 0.f;
    const float* w1p = Wf1 + (size_t)l*RC*DC + t;
    #pragma unroll 8
    for (int r = 0; r < RC; r++) v += cva[r] * w1p[(size_t)r * DC];
    float sg1 = 1.f - 0.5f * expf(-g_s1[be*DC + t]);     // sigmoid(t1) from s1=ssp(t1)
    wk[t] = sg1 * v;
    __syncthreads();
    float u = 0.f;
    const float* w2p = Wf2 + (size_t)l*DC*DC + t;
    #pragma unroll 8
    for (int k = 0; k < DC; k++) u += wk[k] * w2p[(size_t)k * DC];
    float sg2 = 1.f - 0.5f * expf(-g_fb[be*DC + t]);     // sigmoid(t2) from f=ssp(t2)
    g_Fsp[((size_t)b * MAXSP + s) * DC + t] = sg2 * u;
}

// ---------------- gather * f + segment sum (primal + 3 tangents), no atomics ----------------
__global__ void aggK(const int* __restrict__ idx_j) {
    int i = blockIdx.x, b = blockIdx.y, t = threadIdx.x;   // t = 0..127
    const size_t TB = (size_t)BNAT * DC;
    float y = 0.f, y0 = 0.f, y1 = 0.f, y2 = 0.f;
    #pragma unroll 4
    for (int eo = 0; eo < DEGC; eo++) {
        int e = i * DEGC + eo;
        int j = idx_j[e];
        float fv = g_fb[((size_t)b*EC + e)*DC + t];
        size_t xb = ((size_t)b*NATC + j)*DC + t;
        float xv = g_xw4[xb];
        y  += xv * fv;
        y0 += g_xw4[TB   + xb] * fv;
        y1 += g_xw4[2*TB + xb] * fv;
        y2 += g_xw4[3*TB + xb] * fv;
        int s = g_sidx[e];
        if (s >= 0) {
            float Fv = g_Fsp[((size_t)b*MAXSP + s)*DC + t];
            float xF = xv * Fv;
            const float* dd = &g_ddot[((size_t)b*EC + e)*3];
            y0 += dd[0]*xF; y1 += dd[1]*xF; y2 += dd[2]*xF;
        }
    }
    size_t yb = ((size_t)b*NATC + i)*DC + t;
    g_y4[yb] = y; g_y4[TB+yb] = y0; g_y4[2*TB+yb] = y1; g_y4[3*TB+yb] = y2;
}

// ---------------- ssp on primal rows, sigmoid-mask on tangent rows (after Y4@W2) -------------
__global__ void sspTangentK() {
    int idx = blockIdx.x * blockDim.x + threadIdx.x;   // over BNAT*DC
    if (idx >= BNAT * DC) return;
    const size_t TB = (size_t)BNAT * DC;
    float p = g_t34[idx];
    float sg = sigf(p);
    g_t34[idx] = sspf(p);
    g_t34[TB + idx]   *= sg;
    g_t34[2*TB + idx] *= sg;
    g_t34[3*TB + idx] *= sg;
}

// ---------------- final energy tangent reduction ----------------
__global__ void energyK(const float* __restrict__ We, float* __restrict__ out) {
    int b = blockIdx.x, tid = threadIdx.x;
    const size_t TH = (size_t)BNAT * HDC;
    float a0 = 0.f, a1 = 0.f, a2 = 0.f;
    for (int idx = tid; idx < NATC * HDC; idx += 256) {
        int k = idx & (HDC - 1);
        size_t base = (size_t)b * NATC * HDC + idx;
        float p = g_h4[base];
        float w = We[k] * sigf(p);
        a0 += w * g_h4[TH   + base];
        a1 += w * g_h4[2*TH + base];
        a2 += w * g_h4[3*TH + base];
    }
    __shared__ float r0[256], r1[256], r2[256];
    r0[tid] = a0; r1[tid] = a1; r2[tid] = a2;
    __syncthreads();
    for (int s = 128; s > 0; s >>= 1) {
        if (tid < s) { r0[tid] += r0[tid+s]; r1[tid] += r1[tid+s]; r2[tid] += r2[tid+s]; }
        __syncthreads();
    }
    if (tid == 0) {
        out[b*3 + 0] = -r0[0];
        out[b*3 + 1] = -r1[0];
        out[b*3 + 2] = -r2[0];
    }
}

// ---------------- host ----------------
extern "C" void kernel_launch(void* const* d_in, const int* in_sizes, int n_in,
                              void* d_out, int out_size) {
    const float* pos     = (const float*)d_in[0];
    const int*   types   = (const int*)  d_in[1];
    const int*   idx_i   = (const int*)  d_in[2];
    const int*   idx_j   = (const int*)  d_in[3];
    /* d_in[4] = seg_i (== idx_i, unused) */
    const float* emb     = (const float*)d_in[5];
    const float* W1      = (const float*)d_in[6];
    const float* b1      = (const float*)d_in[7];
    const float* Wf1     = (const float*)d_in[8];
    const float* bf1     = (const float*)d_in[9];
    const float* Wf2     = (const float*)d_in[10];
    const float* bf2     = (const float*)d_in[11];
    const float* W2      = (const float*)d_in[12];
    const float* b2      = (const float*)d_in[13];
    const float* W3      = (const float*)d_in[14];
    const float* b3      = (const float*)d_in[15];
    const float* centers = (const float*)d_in[16];
    const float* gammaA  = (const float*)d_in[17];
    const float* Wd      = (const float*)d_in[18];
    const float* bd      = (const float*)d_in[19];
    const float* We      = (const float*)d_in[20];
    float* out = (float*)d_out;

    float *feat4, *xw4, *y4, *t34, *h4, *rbf, *s1, *fb;
    cudaGetSymbolAddress((void**)&feat4, g_feat4);
    cudaGetSymbolAddress((void**)&xw4,  g_xw4);
    cudaGetSymbolAddress((void**)&y4,   g_y4);
    cudaGetSymbolAddress((void**)&t34,  g_t34);
    cudaGetSymbolAddress((void**)&h4,   g_h4);
    cudaGetSymbolAddress((void**)&rbf,  g_rbf);
    cudaGetSymbolAddress((void**)&s1,   g_s1);
    cudaGetSymbolAddress((void**)&fb,   g_fb);

    prepResetK<<<1, 1>>>();
    prepBuildK<<<EC/256, 256>>>(idx_i, idx_j);
    initK<<<(BNAT*DC)/256, 256>>>(emb, types);
    distK<<<(int)(BE/256), 256>>>(pos, idx_i, idx_j);

    for (int l = 0; l < LC; l++) {
        // x = feat @ W1 + b1 (tangents: featdot @ W1)
        sgemmK<<<dim3(M4/128, 1), 256>>>(feat4, W1 + (size_t)l*DC*DC, xw4,
                                         M4, DC, DC, b1 + l*DC, BNAT, nullptr, 0);
        // rbf
        rbfK<<<(int)(BE*RC/256), 256>>>(centers, gammaA, l);
        // s1 = ssp(rbf @ Wf1 + bf1)
        sgemmK<<<dim3((int)(BE/128), 1), 256>>>(rbf, Wf1 + (size_t)l*RC*DC, s1,
                                         (int)BE, DC, RC, bf1 + l*DC, (int)BE, nullptr, 1);
        // f = ssp(s1 @ Wf2 + bf2)
        sgemmK<<<dim3((int)(BE/128), 1), 256>>>(s1, Wf2 + (size_t)l*DC*DC, fb,
                                         (int)BE, DC, DC, bf2 + l*DC, (int)BE, nullptr, 1);
        // F(e) for special edges
        fspK<<<dim3(MAXSP, BC), 128>>>(Wf1, Wf2, centers, gammaA, l);
        // y = segsum(x[j]*f); ydot = segsum(xdot[j]*f + ddot*x[j]*F)
        aggK<<<dim3(NATC, BC), 128>>>(idx_j);
        // t3 = y @ W2 + b2 (tangents raw)
        sgemmK<<<dim3(M4/128, 1), 256>>>(y4, W2 + (size_t)l*DC*DC, t34,
                                         M4, DC, DC, b2 + l*DC, BNAT, nullptr, 0);
        // primal -> ssp(t3); tangents *= sigmoid(t3)
        sspTangentK<<<(BNAT*DC)/256, 256>>>();
        // feat += s3 @ W3 + b3 (tangents: featdot += s3dot @ W3)
        sgemmK<<<dim3(M4/128, 1), 256>>>(t34, W3 + (size_t)l*DC*DC, feat4,
                                         M4, DC, DC, b3 + l*DC, BNAT, feat4, 0);
    }
    // pre = feat @ Wd + bd (raw); tangents: featdot @ Wd
    sgemmK<<<dim3(M4/128, 1), 256>>>(feat4, Wd, h4, M4, HDC, DC, bd, BNAT, nullptr, 0);
    // out[b,0,t] = -sum We[k]*sigmoid(pre)*predot_t
    energyK<<<BC, 256>>>(We, out);
}

// round 3
// speedup vs baseline: 3.0711x; 3.0711x over previous
#include <cuda_runtime.h>
#include <math.h>
#include <stdint.h>

#define NATC 1024
#define DEGC 32
#define DC   128
#define RC   64
#define LC   3
#define BC   16
#define EC   (NATC*DEGC)      /* 32768 */
#define HDC  (DC/2)           /* 64 */
#define BNAT (BC*NATC)        /* 16384 */
#define BE   ((size_t)BC*EC)  /* 524288 */
#define M4   (4*BNAT)         /* 65536 */
#define NQ   4096
#define DMAXF 20.0f
#define LOG2C 0.69314718055994530942f

// ---------------- scratch (allocation-free: __device__ globals) ----------------
__device__ float g_feat4[(size_t)4*BNAT*DC];
__device__ float g_xw4 [(size_t)4*BNAT*DC];
__device__ float g_y4  [(size_t)4*BNAT*DC];
__device__ float g_t34 [(size_t)4*BNAT*DC];
__device__ float g_h4  [(size_t)4*BNAT*HDC];
__device__ float g_d   [BE];
__device__ float g_ddot[(size_t)BE*3];
__device__ float2 g_tab[(size_t)NQ*DC];   // per-layer (rebuilt): (f(d), f'(d)) per dim
__device__ int   g_sflag[EC];

// ---------------- math helpers ----------------
__device__ __forceinline__ float sspf(float x) {
    return fmaxf(x, 0.f) + log1pf(expf(-fabsf(x))) - LOG2C;
}
__device__ __forceinline__ float sigf(float x) {
    return 1.f / (1.f + expf(-x));
}

// ---------------- prep ----------------
__global__ void prepBuildK(const int* __restrict__ idx_i, const int* __restrict__ idx_j) {
    int e = blockIdx.x * blockDim.x + threadIdx.x;
    if (e >= EC) return;
    g_sflag[e] = (idx_i[e] == 0 || idx_j[e] == 0) ? 1 : 0;
}

__global__ void initK(const float* __restrict__ emb, const int* __restrict__ types) {
    int gid = blockIdx.x * blockDim.x + threadIdx.x;      // over BNAT*DC
    if (gid >= BNAT * DC) return;
    int bn = gid / DC;
    int d  = gid - bn * DC;
    int ty = types[bn];
    const size_t TB = (size_t)BNAT * DC;
    g_feat4[gid]        = emb[(size_t)ty * DC + d];
    g_feat4[TB + gid]   = 0.f;
    g_feat4[2*TB + gid] = 0.f;
    g_feat4[3*TB + gid] = 0.f;
}

__global__ void distK(const float* __restrict__ pos,
                      const int* __restrict__ idx_i, const int* __restrict__ idx_j) {
    int gid = blockIdx.x * blockDim.x + threadIdx.x;      // over B*E
    if (gid >= (int)BE) return;
    int b = gid / EC, e = gid - b * EC;
    int i = idx_i[e], j = idx_j[e];
    const float* pi = pos + ((size_t)b * NATC + i) * 3;
    const float* pj = pos + ((size_t)b * NATC + j) * 3;
    float dx = pi[0]-pj[0], dy = pi[1]-pj[1], dz = pi[2]-pj[2];
    float dv = sqrtf(dx*dx + dy*dy + dz*dz + 1e-8f);
    g_d[gid] = dv;
    float c = (float)((i == 0) - (j == 0));
    float inv = c / dv;
    g_ddot[(size_t)gid*3 + 0] = dx * inv;
    g_ddot[(size_t)gid*3 + 1] = dy * inv;
    g_ddot[(size_t)gid*3 + 2] = dz * inv;
}

// ---------------- per-layer edge-MLP lookup table: f(d) and f'(d) ----------------
__global__ void tabK(const float* __restrict__ Wf1, const float* __restrict__ bf1,
                     const float* __restrict__ Wf2, const float* __restrict__ bf2,
                     const float* __restrict__ centers, const float* __restrict__ gammaA, int l) {
    int q = blockIdx.x, t = threadIdx.x;   // q: knot, t: 0..127
    __shared__ float rbf[RC], drb[RC], s1[DC], ds1[DC];
    float dq = q * (DMAXF / (float)(NQ - 1));
    if (t < RC) {
        float gm = gammaA[l*RC + t], cc = centers[l*RC + t];
        float diff = dq - cc;
        float r = expf(-gm * diff * diff);
        rbf[t] = r;
        drb[t] = -2.f * gm * diff * r;
    }
    __syncthreads();
    float t1 = bf1[l*DC + t], dt1 = 0.f;
    const float* w1 = Wf1 + (size_t)l*RC*DC + t;
    #pragma unroll 8
    for (int r = 0; r < RC; r++) {
        float w = w1[(size_t)r * DC];
        t1  += rbf[r] * w;
        dt1 += drb[r] * w;
    }
    s1[t]  = sspf(t1);
    ds1[t] = sigf(t1) * dt1;
    __syncthreads();
    float t2 = bf2[l*DC + t], dt2 = 0.f;
    const float* w2 = Wf2 + (size_t)l*DC*DC + t;
    #pragma unroll 8
    for (int k = 0; k < DC; k++) {
        float w = w2[(size_t)k * DC];
        t2  += s1[k] * w;
        dt2 += ds1[k] * w;
    }
    g_tab[(size_t)q*DC + t] = make_float2(sspf(t2), sigf(t2) * dt2);
}

// ---------------- SGEMM: C[M,N] = A[M,K] @ B[K,N] (+bias rows<biasRows)(+res) ----------
__global__ void __launch_bounds__(256) sgemmK(
    const float* __restrict__ A, const float* __restrict__ Bm, float* __restrict__ C,
    int M, int N, int K, const float* __restrict__ bias, int biasRows,
    const float* __restrict__ res)
{
    __shared__ float As[16][128];
    __shared__ float Bs[16][128];
    const int tid = threadIdx.x;
    const int m0 = blockIdx.x * 128;
    const int n0 = blockIdx.y * 128;
    const int tx = tid & 15, ty = tid >> 4;
    const int aRow = tid >> 2, aCol = (tid & 3) << 2;
    const int bRow = tid >> 5, bCol = (tid & 31) << 2;
    float acc[8][8];
    #pragma unroll
    for (int i = 0; i < 8; i++)
        #pragma unroll
        for (int j = 0; j < 8; j++) acc[i][j] = 0.f;

    for (int k0 = 0; k0 < K; k0 += 16) {
        #pragma unroll
        for (int h = 0; h < 2; h++) {
            int r = aRow + h * 64;
            float4 v = *reinterpret_cast<const float4*>(A + (size_t)(m0 + r) * K + (k0 + aCol));
            As[aCol+0][r] = v.x; As[aCol+1][r] = v.y; As[aCol+2][r] = v.z; As[aCol+3][r] = v.w;
        }
        #pragma unroll
        for (int h = 0; h < 2; h++) {
            int r = bRow + h * 8;
            float4 v = make_float4(0.f, 0.f, 0.f, 0.f);
            if (n0 + bCol < N)
                v = *reinterpret_cast<const float4*>(Bm + (size_t)(k0 + r) * N + (n0 + bCol));
            *reinterpret_cast<float4*>(&Bs[r][bCol]) = v;
        }
        __syncthreads();
        #pragma unroll
        for (int k = 0; k < 16; k++) {
            float4 a0 = *reinterpret_cast<const float4*>(&As[k][ty*8]);
            float4 a1 = *reinterpret_cast<const float4*>(&As[k][ty*8 + 4]);
            float4 b0 = *reinterpret_cast<const float4*>(&Bs[k][tx*8]);
            float4 b1 = *reinterpret_cast<const float4*>(&Bs[k][tx*8 + 4]);
            float av[8] = {a0.x,a0.y,a0.z,a0.w,a1.x,a1.y,a1.z,a1.w};
            float bv[8] = {b0.x,b0.y,b0.z,b0.w,b1.x,b1.y,b1.z,b1.w};
            #pragma unroll
            for (int i = 0; i < 8; i++)
                #pragma unroll
                for (int j = 0; j < 8; j++)
                    acc[i][j] += av[i] * bv[j];
        }
        __syncthreads();
    }
    #pragma unroll
    for (int i = 0; i < 8; i++) {
        int row = m0 + ty*8 + i;
        bool useB = (bias != nullptr) && (row < biasRows);
        #pragma unroll
        for (int j = 0; j < 8; j++) {
            int col = n0 + tx*8 + j;
            if (col < N) {
                float v = acc[i][j];
                if (useB) v += bias[col];
                if (res) v += res[(size_t)row * N + col];
                C[(size_t)row * N + col] = v;
            }
        }
    }
}

// ---------------- fused interp(f) * gather(x) + segment sum (primal + 3 tangents) -------------
__global__ void __launch_bounds__(128) aggK(const int* __restrict__ idx_j) {
    int i = blockIdx.x, b = blockIdx.y, t = threadIdx.x;   // t = 0..127
    const size_t TB = (size_t)BNAT * DC;
    const float invh = (float)(NQ - 1) / DMAXF;
    const float hh   = DMAXF / (float)(NQ - 1);

    __shared__ float sd[DEGC];
    __shared__ int   sj[DEGC];
    __shared__ int   sf[DEGC];
    __shared__ float sdx[DEGC], sdy[DEGC], sdz[DEGC];
    if (t < DEGC) {
        int e = i * DEGC + t;
        sd[t] = g_d[(size_t)b*EC + e];
        sj[t] = idx_j[e];
        sf[t] = g_sflag[e];
        size_t db = ((size_t)b*EC + e) * 3;
        sdx[t] = g_ddot[db + 0];
        sdy[t] = g_ddot[db + 1];
        sdz[t] = g_ddot[db + 2];
    }
    __syncthreads();

    float y = 0.f, y0 = 0.f, y1 = 0.f, y2 = 0.f;
    #pragma unroll 4
    for (int eo = 0; eo < DEGC; eo++) {
        float dv = sd[eo];
        float u = fminf(dv * invh, (float)(NQ - 1));
        int q = (int)u;
        if (q > NQ - 2) q = NQ - 2;
        float w = u - (float)q;
        float2 a0 = g_tab[(size_t)q * DC + t];
        float2 a1 = g_tab[(size_t)(q + 1) * DC + t];
        float w2 = w * w, w3 = w2 * w;
        float h00 = 2.f*w3 - 3.f*w2 + 1.f;
        float h01 = 1.f - h00;
        float h10 = w3 - 2.f*w2 + w;
        float h11 = w3 - w2;
        float fv = h00 * a0.x + h01 * a1.x + hh * (h10 * a0.y + h11 * a1.y);

        int j = sj[eo];
        size_t xb = ((size_t)b*NATC + j)*DC + t;
        float xv = g_xw4[xb];
        y  += xv * fv;
        y0 += g_xw4[TB   + xb] * fv;
        y1 += g_xw4[2*TB + xb] * fv;
        y2 += g_xw4[3*TB + xb] * fv;

        if (sf[eo]) {
            float dcom = 6.f * (w2 - w);
            float F = dcom * (a0.x - a1.x) * invh
                    + (3.f*w2 - 4.f*w + 1.f) * a0.y
                    + (3.f*w2 - 2.f*w) * a1.y;
            float xF = xv * F;
            y0 += sdx[eo] * xF;
            y1 += sdy[eo] * xF;
            y2 += sdz[eo] * xF;
        }
    }
    size_t yb = ((size_t)b*NATC + i)*DC + t;
    g_y4[yb] = y; g_y4[TB+yb] = y0; g_y4[2*TB+yb] = y1; g_y4[3*TB+yb] = y2;
}

// ---------------- ssp on primal rows, sigmoid-mask on tangent rows (after Y4@W2) -------------
__global__ void sspTangentK() {
    int idx = blockIdx.x * blockDim.x + threadIdx.x;   // over BNAT*DC
    if (idx >= BNAT * DC) return;
    const size_t TB = (size_t)BNAT * DC;
    float p = g_t34[idx];
    float sg = sigf(p);
    g_t34[idx] = sspf(p);
    g_t34[TB + idx]   *= sg;
    g_t34[2*TB + idx] *= sg;
    g_t34[3*TB + idx] *= sg;
}

// ---------------- final energy tangent reduction ----------------
__global__ void energyK(const float* __restrict__ We, float* __restrict__ out) {
    int b = blockIdx.x, tid = threadIdx.x;
    const size_t TH = (size_t)BNAT * HDC;
    float a0 = 0.f, a1 = 0.f, a2 = 0.f;
    for (int idx = tid; idx < NATC * HDC; idx += 256) {
        int k = idx & (HDC - 1);
        size_t base = (size_t)b * NATC * HDC + idx;
        float p = g_h4[base];
        float w = We[k] * sigf(p);
        a0 += w * g_h4[TH   + base];
        a1 += w * g_h4[2*TH + base];
        a2 += w * g_h4[3*TH + base];
    }
    __shared__ float r0[256], r1[256], r2[256];
    r0[tid] = a0; r1[tid] = a1; r2[tid] = a2;
    __syncthreads();
    for (int s = 128; s > 0; s >>= 1) {
        if (tid < s) { r0[tid] += r0[tid+s]; r1[tid] += r1[tid+s]; r2[tid] += r2[tid+s]; }
        __syncthreads();
    }
    if (tid == 0) {
        out[b*3 + 0] = -r0[0];
        out[b*3 + 1] = -r1[0];
        out[b*3 + 2] = -r2[0];
    }
}

// ---------------- host ----------------
extern "C" void kernel_launch(void* const* d_in, const int* in_sizes, int n_in,
                              void* d_out, int out_size) {
    const float* pos     = (const float*)d_in[0];
    const int*   types   = (const int*)  d_in[1];
    const int*   idx_i   = (const int*)  d_in[2];
    const int*   idx_j   = (const int*)  d_in[3];
    /* d_in[4] = seg_i (== idx_i, unused) */
    const float* emb     = (const float*)d_in[5];
    const float* W1      = (const float*)d_in[6];
    const float* b1      = (const float*)d_in[7];
    const float* Wf1     = (const float*)d_in[8];
    const float* bf1     = (const float*)d_in[9];
    const float* Wf2     = (const float*)d_in[10];
    const float* bf2     = (const float*)d_in[11];
    const float* W2      = (const float*)d_in[12];
    const float* b2      = (const float*)d_in[13];
    const float* W3      = (const float*)d_in[14];
    const float* b3      = (const float*)d_in[15];
    const float* centers = (const float*)d_in[16];
    const float* gammaA  = (const float*)d_in[17];
    const float* Wd      = (const float*)d_in[18];
    const float* bd      = (const float*)d_in[19];
    const float* We      = (const float*)d_in[20];
    float* out = (float*)d_out;

    float *feat4, *xw4, *y4, *t34, *h4;
    cudaGetSymbolAddress((void**)&feat4, g_feat4);
    cudaGetSymbolAddress((void**)&xw4,  g_xw4);
    cudaGetSymbolAddress((void**)&y4,   g_y4);
    cudaGetSymbolAddress((void**)&t34,  g_t34);
    cudaGetSymbolAddress((void**)&h4,   g_h4);

    prepBuildK<<<EC/256, 256>>>(idx_i, idx_j);
    initK<<<(BNAT*DC)/256, 256>>>(emb, types);
    distK<<<(int)(BE/256), 256>>>(pos, idx_i, idx_j);

    for (int l = 0; l < LC; l++) {
        // x = feat @ W1 + b1 (tangents: featdot @ W1)
        sgemmK<<<dim3(M4/128, 1), 256>>>(feat4, W1 + (size_t)l*DC*DC, xw4,
                                         M4, DC, DC, b1 + l*DC, BNAT, nullptr);
        // edge-MLP lookup table (value + derivative) for this layer
        tabK<<<NQ, DC>>>(Wf1, bf1, Wf2, bf2, centers, gammaA, l);
        // y = segsum(x[j]*f); ydot = segsum(xdot[j]*f + ddot*x[j]*F)
        aggK<<<dim3(NATC, BC), 128>>>(idx_j);
        // t3 = y @ W2 + b2 (tangents raw)
        sgemmK<<<dim3(M4/128, 1), 256>>>(y4, W2 + (size_t)l*DC*DC, t34,
                                         M4, DC, DC, b2 + l*DC, BNAT, nullptr);
        // primal -> ssp(t3); tangents *= sigmoid(t3)
        sspTangentK<<<(BNAT*DC)/256, 256>>>();
        // feat += s3 @ W3 + b3 (tangents: featdot += s3dot @ W3)
        sgemmK<<<dim3(M4/128, 1), 256>>>(t34, W3 + (size_t)l*DC*DC, feat4,
                                         M4, DC, DC, b3 + l*DC, BNAT, feat4);
    }
    // pre = feat @ Wd + bd (raw); tangents: featdot @ Wd
    sgemmK<<<dim3(M4/128, 1), 256>>>(feat4, Wd, h4, M4, HDC, DC, bd, BNAT, nullptr);
    // out[b,0,t] = -sum We[k]*sigmoid(pre)*predot_t
    energyK<<<BC, 256>>>(We, out);
}